// round 13
// baseline (speedup 1.0000x reference)
#include <cuda_runtime.h>
#include <cuda_bf16.h>
#include <math.h>
#include <stdint.h>

// Problem constants
#define T_TOK 2048
#define D_DIM 1024
#define F_DIM 4096
#define E_EXP 8
#define K_TOP 2
#define NENT  (T_TOK * K_TOP)

// TC tiling
#define BM 128
#define BN 128
#define AST 20          // fp32 A staging row stride (floats); 80B
#define BST 132         // fp32 B staging row stride (floats); 528B
#define A_ELE (BM * AST)      // 2560 floats
#define B_ELE (16 * BST)      // 2112 floats
#define AST2 12         // bf16-pair A tile row stride (u32); frag-conflict-free
#define BST2 136        // bf16-pair B tile row stride (u32); frag-conflict-free

// ---------------------------------------------------------------------------
// Scratch (only the round-1/7-proven 64MB h buffer; NO pack arrays)
__device__ float g_h[(size_t)NENT * F_DIM];
__device__ int   g_list[E_EXP * T_TOK];
__device__ float g_wts[NENT];
__device__ int   g_cnt[E_EXP];
__device__ int   g_top1[E_EXP];
__device__ float g_psum[E_EXP];

// ---------------------------------------------------------------------------
__global__ void zero_kernel(float* out, int out_size) {
    int stride = gridDim.x * blockDim.x;
    for (int i = blockIdx.x * blockDim.x + threadIdx.x; i < out_size; i += stride)
        out[i] = 0.0f;
    if (blockIdx.x == 0 && threadIdx.x < E_EXP) {
        g_cnt[threadIdx.x]  = 0;
        g_top1[threadIdx.x] = 0;
        g_psum[threadIdx.x] = 0.0f;
    }
}

// ---------------------------------------------------------------------------
__global__ void gate_kernel(const float* __restrict__ x,
                            const float* __restrict__ Wg,
                            const float* __restrict__ bg) {
    int t = blockIdx.x;
    int w = threadIdx.x >> 5;
    int lane = threadIdx.x & 31;
    const float* xr = x + (size_t)t * D_DIM;

    float s = 0.0f;
    for (int d = lane; d < D_DIM; d += 32)
        s += xr[d] * Wg[d * E_EXP + w];
    #pragma unroll
    for (int o = 16; o; o >>= 1) s += __shfl_xor_sync(0xffffffffu, s, o);

    __shared__ float lg[E_EXP];
    if (lane == 0) lg[w] = s + bg[w];
    __syncthreads();

    if (threadIdx.x == 0) {
        float mx = lg[0];
        #pragma unroll
        for (int e = 1; e < E_EXP; e++) mx = fmaxf(mx, lg[e]);
        float p[E_EXP];
        float sum = 0.0f;
        #pragma unroll
        for (int e = 0; e < E_EXP; e++) { p[e] = __expf(lg[e] - mx); sum += p[e]; }
        float inv = 1.0f / sum;
        #pragma unroll
        for (int e = 0; e < E_EXP; e++) { p[e] *= inv; atomicAdd(&g_psum[e], p[e]); }

        int i0 = 0;
        #pragma unroll
        for (int e = 1; e < E_EXP; e++) if (p[e] > p[i0]) i0 = e;
        int i1 = -1;
        #pragma unroll
        for (int e = 0; e < E_EXP; e++) {
            if (e == i0) continue;
            if (i1 < 0 || p[e] > p[i1]) i1 = e;
        }
        atomicAdd(&g_top1[i0], 1);

        int pos0 = atomicAdd(&g_cnt[i0], 1);
        g_list[i0 * T_TOK + pos0] = t * 2 + 0;
        g_wts[t * 2 + 0] = p[i0];
        int pos1 = atomicAdd(&g_cnt[i1], 1);
        g_list[i1 * T_TOK + pos1] = t * 2 + 1;
        g_wts[t * 2 + 1] = p[i1];
    }
}

// ---------------------------------------------------------------------------
__global__ void aux_kernel(float* out, int out_size) {
    if (threadIdx.x == 0 && blockIdx.x == 0) {
        float aux = 0.0f;
        #pragma unroll
        for (int e = 0; e < E_EXP; e++)
            aux += ((float)g_top1[e] / ((float)T_TOK + 1e-8f)) *
                   (g_psum[e] / (float)T_TOK);
        aux *= (float)E_EXP;
        if (out_size > T_TOK * D_DIM) out[T_TOK * D_DIM] = aux;
    }
}

// ---------------------------------------------------------------------------
__device__ __forceinline__ void mma16816(float* d, const uint32_t* a, const uint32_t* b) {
    asm volatile("mma.sync.aligned.m16n8k16.row.col.f32.bf16.bf16.f32 "
                 "{%0,%1,%2,%3}, {%4,%5,%6,%7}, {%8,%9}, {%0,%1,%2,%3};\n"
                 : "+f"(d[0]), "+f"(d[1]), "+f"(d[2]), "+f"(d[3])
                 : "r"(a[0]), "r"(a[1]), "r"(a[2]), "r"(a[3]), "r"(b[0]), "r"(b[1]));
}

__device__ __forceinline__ void cp16(unsigned sdst, const void* gsrc) {
    asm volatile("cp.async.cg.shared.global [%0], [%1], 16;\n" :: "r"(sdst), "l"(gsrc));
}
__device__ __forceinline__ void cp_commit() { asm volatile("cp.async.commit_group;\n" ::: "memory"); }
template <int N>
__device__ __forceinline__ void cp_wait() { asm volatile("cp.async.wait_group %0;\n" :: "n"(N) : "memory"); }

// split two floats -> packed bf16x2 hi (first arg = low half) + packed bf16x2 lo
__device__ __forceinline__ void split2(float f0, float f1, uint32_t& hi, uint32_t& lo) {
    __nv_bfloat162 h = __floats2bfloat162_rn(f0, f1);
    float h0 = __bfloat162float(h.x), h1 = __bfloat162float(h.y);
    __nv_bfloat162 l = __floats2bfloat162_rn(f0 - h0, f1 - h1);
    hi = *(uint32_t*)&h;
    lo = *(uint32_t*)&l;
}

// ---------------------------------------------------------------------------
// TC core: cp.async fp32 tiles (single staging buffer) -> per-CTA split into
// bf16-pair u32 tiles -> pure-LDS fragments -> 3 split-product MMAs.
// A rows gathered (per-thread base ptr pa, row length KDIM floats).
// B = weights [k][n] row-major (bbase = &W[e][0][n0], row stride NDIM floats).
template <int KDIM, int NDIM>
__device__ __forceinline__ void tc_core(
    const float* pa,                 // this thread's A row base (row = tid>>1)
    const float* bbase,              // W + e*K*N + n0
    float* Afp, float* Bfp,          // fp32 staging: [A_ELE], [B_ELE]
    uint32_t* sAh, uint32_t* sAl,    // bf16-pair tiles: [BM*AST2]
    uint32_t* sBh, uint32_t* sBl,    // [8*BST2]
    int tid, float acc[4][4][4])
{
    // cp.async loader mapping (identical to proven R7)
    int arow = tid >> 1, afo = (tid & 1) * 8;
    unsigned aS = (unsigned)__cvta_generic_to_shared(Afp);
    unsigned bS = (unsigned)__cvta_generic_to_shared(Bfp);
    unsigned adst = aS + (arow * AST + afo) * 4;
    int bkr = tid >> 4, bc = (tid & 15) * 4;
    unsigned bdst = bS + (bkr * BST + bc) * 4;

    // split-stage mapping
    int srow = tid >> 1, skh = (tid & 1) * 8;       // A: row, k-half (8 floats)
    int sk2 = tid & 7, snb = ((tid >> 3) & 31) * 4; // B: k2 row, 4 n's

    int lane = tid & 31, warp = tid >> 5;
    int wm = (warp & 1) * 64, wn = (warp >> 1) * 32;
    int g = lane >> 2, tig = lane & 3;

    const int NS = KDIM / 16;

    auto do_split = [&]() {
        // A: 8 floats = 4 float2 -> 4 hi/lo u32
        #pragma unroll
        for (int j = 0; j < 4; j++) {
            float2 v = *(const float2*)(Afp + srow * AST + skh + 2 * j);
            uint32_t hi, lo;
            split2(v.x, v.y, hi, lo);
            sAh[srow * AST2 + (skh >> 1) + j] = hi;
            sAl[srow * AST2 + (skh >> 1) + j] = lo;
        }
        // B: 4 n's, pair k rows 2*sk2 (even) and 2*sk2+1 (odd)
        float4 r0 = *(const float4*)(Bfp + (2 * sk2) * BST + snb);
        float4 r1 = *(const float4*)(Bfp + (2 * sk2 + 1) * BST + snb);
        uint32_t hi, lo;
        split2(r0.x, r1.x, hi, lo); sBh[sk2 * BST2 + snb + 0] = hi; sBl[sk2 * BST2 + snb + 0] = lo;
        split2(r0.y, r1.y, hi, lo); sBh[sk2 * BST2 + snb + 1] = hi; sBl[sk2 * BST2 + snb + 1] = lo;
        split2(r0.z, r1.z, hi, lo); sBh[sk2 * BST2 + snb + 2] = hi; sBl[sk2 * BST2 + snb + 2] = lo;
        split2(r0.w, r1.w, hi, lo); sBh[sk2 * BST2 + snb + 3] = hi; sBl[sk2 * BST2 + snb + 3] = lo;
    };

    // preload + split slab 0
    cp16(adst, pa + afo);
    cp16(adst + 16, pa + afo + 4);
    cp16(bdst, bbase + (size_t)bkr * NDIM + bc);
    cp16(bdst + 256, bbase + (size_t)bkr * NDIM + bc + 64);
    cp_commit();
    cp_wait<0>();
    __syncthreads();
    do_split();
    __syncthreads();

    for (int s = 0; s < NS; s++) {
        // prefetch fp32 slab s+1 (overlaps MMA below; staging buffer was fully
        // consumed by the split of slab s, which completed before this point)
        if (s + 1 < NS) {
            int kk = (s + 1) * 16;
            cp16(adst, pa + kk + afo);
            cp16(adst + 16, pa + kk + afo + 4);
            const float* bsrc = bbase + (size_t)(kk + bkr) * NDIM + bc;
            cp16(bdst, bsrc);
            cp16(bdst + 256, bsrc + 64);
            cp_commit();
        }

        // MMA on current bf16 tiles (slab s) — pure LDS, zero cvt
        uint32_t ah[4][4], al[4][4];
        #pragma unroll
        for (int mi = 0; mi < 4; mi++) {
            const uint32_t* p = sAh + (wm + mi * 16 + g) * AST2 + tig;
            ah[mi][0] = p[0];                // (m,   k=2tig)
            ah[mi][1] = p[8 * AST2];         // (m+8, k=2tig)
            ah[mi][2] = p[4];                // (m,   k=2tig+8)
            ah[mi][3] = p[8 * AST2 + 4];
            const uint32_t* q = sAl + (wm + mi * 16 + g) * AST2 + tig;
            al[mi][0] = q[0];
            al[mi][1] = q[8 * AST2];
            al[mi][2] = q[4];
            al[mi][3] = q[8 * AST2 + 4];
        }
        #pragma unroll
        for (int nj = 0; nj < 4; nj++) {
            int nn = wn + nj * 8 + g;
            uint32_t bh[2], bl[2];
            bh[0] = sBh[tig * BST2 + nn];          // k=2tig, 2tig+1
            bh[1] = sBh[(tig + 4) * BST2 + nn];    // k=2tig+8, +9
            bl[0] = sBl[tig * BST2 + nn];
            bl[1] = sBl[(tig + 4) * BST2 + nn];
            #pragma unroll
            for (int mi = 0; mi < 4; mi++) {
                mma16816(acc[mi][nj], ah[mi], bh);   // hi*hi
                mma16816(acc[mi][nj], ah[mi], bl);   // hi*lo
                mma16816(acc[mi][nj], al[mi], bh);   // lo*hi
            }
        }

        if (s + 1 < NS) {
            cp_wait<0>();
            __syncthreads();   // fp32 slab s+1 visible AND all MMA frag reads of slab s done
            do_split();        // overwrite bf16 tiles with slab s+1
            __syncthreads();
        }
    }
}

// ---------------------------------------------------------------------------
// GEMM1: g_h[entry][f] = relu( x[token] @ W1[e] + b1[e] )
__global__ __launch_bounds__(256, 2)
void gemm1_tc_kernel(const float* __restrict__ x,
                     const float* __restrict__ W1,
                     const float* __restrict__ b1) {
    int e = blockIdx.z;
    int n = g_cnt[e];
    int m0 = blockIdx.x * BM;
    if (m0 >= n) return;
    int n0 = blockIdx.y * BN;

    __shared__ int rows_s[BM];
    __shared__ __align__(16) float Afp[A_ELE];
    __shared__ __align__(16) float Bfp[B_ELE];
    __shared__ __align__(16) uint32_t sAh[BM * AST2];
    __shared__ __align__(16) uint32_t sAl[BM * AST2];
    __shared__ __align__(16) uint32_t sBh[8 * BST2];
    __shared__ __align__(16) uint32_t sBl[8 * BST2];

    int tid = threadIdx.x;
    if (tid < BM) {
        int r = m0 + tid;
        rows_s[tid] = (r < n) ? g_list[e * T_TOK + r] : g_list[e * T_TOK];
    }
    __syncthreads();

    const float* pa = x + (size_t)(rows_s[tid >> 1] >> 1) * D_DIM;
    const float* bbase = W1 + (size_t)e * D_DIM * F_DIM + n0;

    float acc[4][4][4] = {};
    tc_core<D_DIM, F_DIM>(pa, bbase, Afp, Bfp, sAh, sAl, sBh, sBl, tid, acc);

    int lane = tid & 31, warp = tid >> 5;
    int wm = (warp & 1) * 64, wn = (warp >> 1) * 32;
    int g = lane >> 2, tig = lane & 3;
    const float* b1g = b1 + (size_t)e * F_DIM;
    #pragma unroll
    for (int mi = 0; mi < 4; mi++) {
        #pragma unroll
        for (int half = 0; half < 2; half++) {
            int rl = wm + mi * 16 + g + half * 8;
            if (m0 + rl >= n) continue;
            int entry = rows_s[rl];
            float* hrow = g_h + (size_t)entry * F_DIM;
            #pragma unroll
            for (int ni = 0; ni < 4; ni++) {
                int col = n0 + wn + ni * 8 + tig * 2;
                hrow[col]     = fmaxf(acc[mi][ni][half * 2 + 0] + b1g[col], 0.0f);
                hrow[col + 1] = fmaxf(acc[mi][ni][half * 2 + 1] + b1g[col + 1], 0.0f);
            }
        }
    }
}

// ---------------------------------------------------------------------------
// GEMM2: out[t] += wt * ( g_h[entry] @ W2[e] + b2[e] )
__global__ __launch_bounds__(256, 2)
void gemm2_tc_kernel(const float* __restrict__ W2,
                     const float* __restrict__ b2,
                     float* __restrict__ out) {
    int e = blockIdx.z;
    int n = g_cnt[e];
    int m0 = blockIdx.x * BM;
    if (m0 >= n) return;
    int n0 = blockIdx.y * BN;

    __shared__ int rows_s[BM];
    __shared__ __align__(16) float Afp[A_ELE];
    __shared__ __align__(16) float Bfp[B_ELE];
    __shared__ __align__(16) uint32_t sAh[BM * AST2];
    __shared__ __align__(16) uint32_t sAl[BM * AST2];
    __shared__ __align__(16) uint32_t sBh[8 * BST2];
    __shared__ __align__(16) uint32_t sBl[8 * BST2];

    int tid = threadIdx.x;
    if (tid < BM) {
        int r = m0 + tid;
        rows_s[tid] = (r < n) ? g_list[e * T_TOK + r] : g_list[e * T_TOK];
    }
    __syncthreads();

    const float* pa = g_h + (size_t)rows_s[tid >> 1] * F_DIM;
    const float* bbase = W2 + (size_t)e * F_DIM * D_DIM + n0;

    float acc[4][4][4] = {};
    tc_core<F_DIM, D_DIM>(pa, bbase, Afp, Bfp, sAh, sAl, sBh, sBl, tid, acc);

    int lane = tid & 31, warp = tid >> 5;
    int wm = (warp & 1) * 64, wn = (warp >> 1) * 32;
    int g = lane >> 2, tig = lane & 3;
    const float* b2g = b2 + (size_t)e * D_DIM;
    #pragma unroll
    for (int mi = 0; mi < 4; mi++) {
        #pragma unroll
        for (int half = 0; half < 2; half++) {
            int rl = wm + mi * 16 + g + half * 8;
            if (m0 + rl >= n) continue;
            int entry = rows_s[rl];
            int t = entry >> 1;
            float wt = g_wts[entry];
            float* orow = out + (size_t)t * D_DIM;
            #pragma unroll
            for (int ni = 0; ni < 4; ni++) {
                int col = n0 + wn + ni * 8 + tig * 2;
                float v0 = (acc[mi][ni][half * 2 + 0] + b2g[col]) * wt;
                float v1 = (acc[mi][ni][half * 2 + 1] + b2g[col + 1]) * wt;
                atomicAdd(&orow[col], v0);
                atomicAdd(&orow[col + 1], v1);
            }
        }
    }
}

// ---------------------------------------------------------------------------
extern "C" void kernel_launch(void* const* d_in, const int* in_sizes, int n_in,
                              void* d_out, int out_size) {
    const float* x  = (const float*)d_in[0];
    const float* Wg = (const float*)d_in[1];
    const float* bg = (const float*)d_in[2];
    const float* W1 = (const float*)d_in[3];
    const float* b1 = (const float*)d_in[4];
    const float* W2 = (const float*)d_in[5];
    const float* b2 = (const float*)d_in[6];
    float* out = (float*)d_out;

    zero_kernel<<<256, 256>>>(out, out_size);
    gate_kernel<<<T_TOK, 256>>>(x, Wg, bg);
    aux_kernel<<<1, 32>>>(out, out_size);

    dim3 g1(T_TOK / BM, F_DIM / BN, E_EXP);      // (16, 32, 8)
    gemm1_tc_kernel<<<g1, 256>>>(x, W1, b1);

    dim3 g2(T_TOK / BM, D_DIM / BN, E_EXP);      // (16, 8, 8)
    gemm2_tc_kernel<<<g2, 256>>>(W2, b2, out);
}

// round 14
// speedup vs baseline: 1.2494x; 1.2494x over previous
#include <cuda_runtime.h>
#include <cuda_bf16.h>
#include <math.h>
#include <stdint.h>

// Problem constants
#define T_TOK 2048
#define D_DIM 1024
#define F_DIM 4096
#define E_EXP 8
#define K_TOP 2
#define NENT  (T_TOK * K_TOP)

// TC tiling
#define BM 128
#define BN 128
#define AST2 12         // bf16-pair A tile row stride (u32); frag-conflict-free
#define BST2 136        // bf16-pair B tile row stride (u32); frag-conflict-free
#define A_T (BM * AST2)     // 1536 u32 per buffer
#define B_T (8 * BST2)      // 1088 u32 per buffer

// ---------------------------------------------------------------------------
// Scratch (proven set only)
__device__ float g_h[(size_t)NENT * F_DIM];
__device__ int   g_list[E_EXP * T_TOK];
__device__ float g_wts[NENT];
__device__ int   g_cnt[E_EXP];
__device__ int   g_top1[E_EXP];
__device__ float g_psum[E_EXP];

// ---------------------------------------------------------------------------
__global__ void zero_kernel(float* out, int out_size) {
    int stride = gridDim.x * blockDim.x;
    for (int i = blockIdx.x * blockDim.x + threadIdx.x; i < out_size; i += stride)
        out[i] = 0.0f;
    if (blockIdx.x == 0 && threadIdx.x < E_EXP) {
        g_cnt[threadIdx.x]  = 0;
        g_top1[threadIdx.x] = 0;
        g_psum[threadIdx.x] = 0.0f;
    }
}

// ---------------------------------------------------------------------------
__global__ void gate_kernel(const float* __restrict__ x,
                            const float* __restrict__ Wg,
                            const float* __restrict__ bg) {
    int t = blockIdx.x;
    int w = threadIdx.x >> 5;
    int lane = threadIdx.x & 31;
    const float* xr = x + (size_t)t * D_DIM;

    float s = 0.0f;
    for (int d = lane; d < D_DIM; d += 32)
        s += xr[d] * Wg[d * E_EXP + w];
    #pragma unroll
    for (int o = 16; o; o >>= 1) s += __shfl_xor_sync(0xffffffffu, s, o);

    __shared__ float lg[E_EXP];
    if (lane == 0) lg[w] = s + bg[w];
    __syncthreads();

    if (threadIdx.x == 0) {
        float mx = lg[0];
        #pragma unroll
        for (int e = 1; e < E_EXP; e++) mx = fmaxf(mx, lg[e]);
        float p[E_EXP];
        float sum = 0.0f;
        #pragma unroll
        for (int e = 0; e < E_EXP; e++) { p[e] = __expf(lg[e] - mx); sum += p[e]; }
        float inv = 1.0f / sum;
        #pragma unroll
        for (int e = 0; e < E_EXP; e++) { p[e] *= inv; atomicAdd(&g_psum[e], p[e]); }

        int i0 = 0;
        #pragma unroll
        for (int e = 1; e < E_EXP; e++) if (p[e] > p[i0]) i0 = e;
        int i1 = -1;
        #pragma unroll
        for (int e = 0; e < E_EXP; e++) {
            if (e == i0) continue;
            if (i1 < 0 || p[e] > p[i1]) i1 = e;
        }
        atomicAdd(&g_top1[i0], 1);

        int pos0 = atomicAdd(&g_cnt[i0], 1);
        g_list[i0 * T_TOK + pos0] = t * 2 + 0;
        g_wts[t * 2 + 0] = p[i0];
        int pos1 = atomicAdd(&g_cnt[i1], 1);
        g_list[i1 * T_TOK + pos1] = t * 2 + 1;
        g_wts[t * 2 + 1] = p[i1];
    }
}

// ---------------------------------------------------------------------------
__global__ void aux_kernel(float* out, int out_size) {
    if (threadIdx.x == 0 && blockIdx.x == 0) {
        float aux = 0.0f;
        #pragma unroll
        for (int e = 0; e < E_EXP; e++)
            aux += ((float)g_top1[e] / ((float)T_TOK + 1e-8f)) *
                   (g_psum[e] / (float)T_TOK);
        aux *= (float)E_EXP;
        if (out_size > T_TOK * D_DIM) out[T_TOK * D_DIM] = aux;
    }
}

// ---------------------------------------------------------------------------
__device__ __forceinline__ void mma16816(float* d, const uint32_t* a, const uint32_t* b) {
    asm volatile("mma.sync.aligned.m16n8k16.row.col.f32.bf16.bf16.f32 "
                 "{%0,%1,%2,%3}, {%4,%5,%6,%7}, {%8,%9}, {%0,%1,%2,%3};\n"
                 : "+f"(d[0]), "+f"(d[1]), "+f"(d[2]), "+f"(d[3])
                 : "r"(a[0]), "r"(a[1]), "r"(a[2]), "r"(a[3]), "r"(b[0]), "r"(b[1]));
}

// split two floats -> packed bf16x2 hi (first arg = low half) + packed bf16x2 lo
__device__ __forceinline__ void split2(float f0, float f1, uint32_t& hi, uint32_t& lo) {
    __nv_bfloat162 h = __floats2bfloat162_rn(f0, f1);
    float h0 = __bfloat162float(h.x), h1 = __bfloat162float(h.y);
    __nv_bfloat162 l = __floats2bfloat162_rn(f0 - h0, f1 - h1);
    hi = *(uint32_t*)&h;
    lo = *(uint32_t*)&l;
}

// ---------------------------------------------------------------------------
// TC core: register-staged fp32 global loads -> split once per CTA into
// DOUBLE-BUFFERED bf16-pair u32 tiles -> pure-LDS fragments -> 3 MMAs each.
// One __syncthreads per k16 slab; LDG(s+1) overlaps MMA(s).
template <int KDIM, int NDIM>
__device__ __forceinline__ void tc_core(
    const float* pa,                 // this thread's A row base (row = tid>>1)
    const float* bbase,              // W + e*K*N + n0
    uint32_t* sAh, uint32_t* sAl,    // [2][A_T]
    uint32_t* sBh, uint32_t* sBl,    // [2][B_T]
    int tid, float acc[4][4][4])
{
    // A loader: row = tid>>1, k-half = (tid&1)*8 floats
    int arow = tid >> 1, ak = (tid & 1) * 8;
    // B loader: warp w covers k-pair row w (k = 2w, 2w+1), lane covers 4 n
    int bk2 = tid >> 5, bn = (tid & 31) * 4;

    int lane = tid & 31, warp = tid >> 5;
    int wm = (warp & 1) * 64, wn = (warp >> 1) * 32;
    int g = lane >> 2, tig = lane & 3;

    const int NS = KDIM / 16;

    float4 ra0, ra1, rb0, rb1;

    auto load_regs = [&](int s) {
        int kk = s * 16;
        ra0 = *(const float4*)(pa + kk + ak);
        ra1 = *(const float4*)(pa + kk + ak + 4);
        const float* bs = bbase + (size_t)(kk + 2 * bk2) * NDIM + bn;
        rb0 = *(const float4*)bs;           // k even row
        rb1 = *(const float4*)(bs + NDIM);  // k odd row
    };
    auto split_store = [&](int buf) {
        uint32_t* Ah = sAh + buf * A_T;
        uint32_t* Al = sAl + buf * A_T;
        uint32_t* Bh = sBh + buf * B_T;
        uint32_t* Bl = sBl + buf * B_T;
        uint4 hv, lv;
        // A: pair along k within the row
        split2(ra0.x, ra0.y, hv.x, lv.x);
        split2(ra0.z, ra0.w, hv.y, lv.y);
        split2(ra1.x, ra1.y, hv.z, lv.z);
        split2(ra1.z, ra1.w, hv.w, lv.w);
        *(uint4*)(Ah + arow * AST2 + (ak >> 1)) = hv;
        *(uint4*)(Al + arow * AST2 + (ak >> 1)) = lv;
        // B: pair across adjacent k rows for each n
        split2(rb0.x, rb1.x, hv.x, lv.x);
        split2(rb0.y, rb1.y, hv.y, lv.y);
        split2(rb0.z, rb1.z, hv.z, lv.z);
        split2(rb0.w, rb1.w, hv.w, lv.w);
        *(uint4*)(Bh + bk2 * BST2 + bn) = hv;
        *(uint4*)(Bl + bk2 * BST2 + bn) = lv;
    };

    // prologue: slab 0 -> buf 0
    load_regs(0);
    split_store(0);
    __syncthreads();

    for (int s = 0; s < NS; s++) {
        int buf = s & 1;
        if (s + 1 < NS) load_regs(s + 1);   // LDG latency overlaps MMA below

        const uint32_t* Ah = sAh + buf * A_T;
        const uint32_t* Al = sAl + buf * A_T;
        const uint32_t* Bh = sBh + buf * B_T;
        const uint32_t* Bl = sBl + buf * B_T;

        // B fragments for the whole slab (8+8 u32)
        uint32_t bh[4][2], bl[4][2];
        #pragma unroll
        for (int nj = 0; nj < 4; nj++) {
            int nn = wn + nj * 8 + g;
            bh[nj][0] = Bh[tig * BST2 + nn];         // k=2tig, 2tig+1
            bh[nj][1] = Bh[(tig + 4) * BST2 + nn];   // k=2tig+8, +9
            bl[nj][0] = Bl[tig * BST2 + nn];
            bl[nj][1] = Bl[(tig + 4) * BST2 + nn];
        }
        // mi-outer: A fragments live only per-mi (8 u32)
        #pragma unroll
        for (int mi = 0; mi < 4; mi++) {
            uint32_t ah[4], al[4];
            const uint32_t* p = Ah + (wm + mi * 16 + g) * AST2 + tig;
            ah[0] = p[0];                 // (m,   k=2tig)
            ah[1] = p[8 * AST2];          // (m+8, k=2tig)
            ah[2] = p[4];                 // (m,   k=2tig+8)
            ah[3] = p[8 * AST2 + 4];
            const uint32_t* q = Al + (wm + mi * 16 + g) * AST2 + tig;
            al[0] = q[0];
            al[1] = q[8 * AST2];
            al[2] = q[4];
            al[3] = q[8 * AST2 + 4];
            #pragma unroll
            for (int nj = 0; nj < 4; nj++) {
                mma16816(acc[mi][nj], ah, bh[nj]);   // hi*hi
                mma16816(acc[mi][nj], ah, bl[nj]);   // hi*lo
                mma16816(acc[mi][nj], al, bh[nj]);   // lo*hi
            }
        }

        if (s + 1 < NS) {
            split_store(buf ^ 1);   // safe: barrier at end of slab s-1 ordered
                                    // all reads of buf^1 before these writes
            __syncthreads();
        }
    }
}

// ---------------------------------------------------------------------------
// GEMM1: g_h[entry][f] = relu( x[token] @ W1[e] + b1[e] )
__global__ __launch_bounds__(256, 2)
void gemm1_tc_kernel(const float* __restrict__ x,
                     const float* __restrict__ W1,
                     const float* __restrict__ b1) {
    int e = blockIdx.z;
    int n = g_cnt[e];
    int m0 = blockIdx.x * BM;
    if (m0 >= n) return;
    int n0 = blockIdx.y * BN;

    __shared__ int rows_s[BM];
    __shared__ __align__(16) uint32_t sAh[2 * A_T];
    __shared__ __align__(16) uint32_t sAl[2 * A_T];
    __shared__ __align__(16) uint32_t sBh[2 * B_T];
    __shared__ __align__(16) uint32_t sBl[2 * B_T];

    int tid = threadIdx.x;
    if (tid < BM) {
        int r = m0 + tid;
        rows_s[tid] = (r < n) ? g_list[e * T_TOK + r] : g_list[e * T_TOK];
    }
    __syncthreads();

    const float* pa = x + (size_t)(rows_s[tid >> 1] >> 1) * D_DIM;
    const float* bbase = W1 + (size_t)e * D_DIM * F_DIM + n0;

    float acc[4][4][4] = {};
    tc_core<D_DIM, F_DIM>(pa, bbase, sAh, sAl, sBh, sBl, tid, acc);

    int lane = tid & 31, warp = tid >> 5;
    int wm = (warp & 1) * 64, wn = (warp >> 1) * 32;
    int g = lane >> 2, tig = lane & 3;
    const float* b1g = b1 + (size_t)e * F_DIM;
    #pragma unroll
    for (int mi = 0; mi < 4; mi++) {
        #pragma unroll
        for (int half = 0; half < 2; half++) {
            int rl = wm + mi * 16 + g + half * 8;
            if (m0 + rl >= n) continue;
            int entry = rows_s[rl];
            float* hrow = g_h + (size_t)entry * F_DIM;
            #pragma unroll
            for (int ni = 0; ni < 4; ni++) {
                int col = n0 + wn + ni * 8 + tig * 2;
                hrow[col]     = fmaxf(acc[mi][ni][half * 2 + 0] + b1g[col], 0.0f);
                hrow[col + 1] = fmaxf(acc[mi][ni][half * 2 + 1] + b1g[col + 1], 0.0f);
            }
        }
    }
}

// ---------------------------------------------------------------------------
// GEMM2: out[t] += wt * ( g_h[entry] @ W2[e] + b2[e] )
__global__ __launch_bounds__(256, 2)
void gemm2_tc_kernel(const float* __restrict__ W2,
                     const float* __restrict__ b2,
                     float* __restrict__ out) {
    int e = blockIdx.z;
    int n = g_cnt[e];
    int m0 = blockIdx.x * BM;
    if (m0 >= n) return;
    int n0 = blockIdx.y * BN;

    __shared__ int rows_s[BM];
    __shared__ __align__(16) uint32_t sAh[2 * A_T];
    __shared__ __align__(16) uint32_t sAl[2 * A_T];
    __shared__ __align__(16) uint32_t sBh[2 * B_T];
    __shared__ __align__(16) uint32_t sBl[2 * B_T];

    int tid = threadIdx.x;
    if (tid < BM) {
        int r = m0 + tid;
        rows_s[tid] = (r < n) ? g_list[e * T_TOK + r] : g_list[e * T_TOK];
    }
    __syncthreads();

    const float* pa = g_h + (size_t)rows_s[tid >> 1] * F_DIM;
    const float* bbase = W2 + (size_t)e * F_DIM * D_DIM + n0;

    float acc[4][4][4] = {};
    tc_core<F_DIM, D_DIM>(pa, bbase, sAh, sAl, sBh, sBl, tid, acc);

    int lane = tid & 31, warp = tid >> 5;
    int wm = (warp & 1) * 64, wn = (warp >> 1) * 32;
    int g = lane >> 2, tig = lane & 3;
    const float* b2g = b2 + (size_t)e * D_DIM;
    #pragma unroll
    for (int mi = 0; mi < 4; mi++) {
        #pragma unroll
        for (int half = 0; half < 2; half++) {
            int rl = wm + mi * 16 + g + half * 8;
            if (m0 + rl >= n) continue;
            int entry = rows_s[rl];
            int t = entry >> 1;
            float wt = g_wts[entry];
            float* orow = out + (size_t)t * D_DIM;
            #pragma unroll
            for (int ni = 0; ni < 4; ni++) {
                int col = n0 + wn + ni * 8 + tig * 2;
                float v0 = (acc[mi][ni][half * 2 + 0] + b2g[col]) * wt;
                float v1 = (acc[mi][ni][half * 2 + 1] + b2g[col + 1]) * wt;
                atomicAdd(&orow[col], v0);
                atomicAdd(&orow[col + 1], v1);
            }
        }
    }
}

// ---------------------------------------------------------------------------
extern "C" void kernel_launch(void* const* d_in, const int* in_sizes, int n_in,
                              void* d_out, int out_size) {
    const float* x  = (const float*)d_in[0];
    const float* Wg = (const float*)d_in[1];
    const float* bg = (const float*)d_in[2];
    const float* W1 = (const float*)d_in[3];
    const float* b1 = (const float*)d_in[4];
    const float* W2 = (const float*)d_in[5];
    const float* b2 = (const float*)d_in[6];
    float* out = (float*)d_out;

    zero_kernel<<<256, 256>>>(out, out_size);
    gate_kernel<<<T_TOK, 256>>>(x, Wg, bg);
    aux_kernel<<<1, 32>>>(out, out_size);

    dim3 g1(T_TOK / BM, F_DIM / BN, E_EXP);      // (16, 32, 8)
    gemm1_tc_kernel<<<g1, 256>>>(x, W1, b1);

    dim3 g2(T_TOK / BM, D_DIM / BN, E_EXP);      // (16, 8, 8)
    gemm2_tc_kernel<<<g2, 256>>>(W2, b2, out);
}

// round 15
// speedup vs baseline: 1.3619x; 1.0900x over previous
#include <cuda_runtime.h>
#include <cuda_bf16.h>
#include <math.h>
#include <stdint.h>

// Problem constants
#define T_TOK 2048
#define D_DIM 1024
#define F_DIM 4096
#define E_EXP 8
#define K_TOP 2
#define NENT  (T_TOK * K_TOP)

// TC tiling
#define BM 128
#define BN 128
#define AST2 12         // bf16-pair A tile row stride (u32); LDSM-conflict-free
#define BST2 136        // bf16-pair B tile row stride (u32); frag-conflict-free
#define A_T (BM * AST2)     // 1536 u32 per buffer
#define B_T (8 * BST2)      // 1088 u32 per buffer

// ---------------------------------------------------------------------------
// Scratch (proven set only)
__device__ float g_h[(size_t)NENT * F_DIM];
__device__ int   g_list[E_EXP * T_TOK];
__device__ float g_wts[NENT];
__device__ int   g_cnt[E_EXP];
__device__ int   g_top1[E_EXP];
__device__ float g_psum[E_EXP];

// ---------------------------------------------------------------------------
__global__ void zero_kernel(float* out, int out_size) {
    int stride = gridDim.x * blockDim.x;
    for (int i = blockIdx.x * blockDim.x + threadIdx.x; i < out_size; i += stride)
        out[i] = 0.0f;
    if (blockIdx.x == 0 && threadIdx.x < E_EXP) {
        g_cnt[threadIdx.x]  = 0;
        g_top1[threadIdx.x] = 0;
        g_psum[threadIdx.x] = 0.0f;
    }
}

// ---------------------------------------------------------------------------
__global__ void gate_kernel(const float* __restrict__ x,
                            const float* __restrict__ Wg,
                            const float* __restrict__ bg) {
    int t = blockIdx.x;
    int w = threadIdx.x >> 5;
    int lane = threadIdx.x & 31;
    const float* xr = x + (size_t)t * D_DIM;

    float s = 0.0f;
    for (int d = lane; d < D_DIM; d += 32)
        s += xr[d] * Wg[d * E_EXP + w];
    #pragma unroll
    for (int o = 16; o; o >>= 1) s += __shfl_xor_sync(0xffffffffu, s, o);

    __shared__ float lg[E_EXP];
    if (lane == 0) lg[w] = s + bg[w];
    __syncthreads();

    if (threadIdx.x == 0) {
        float mx = lg[0];
        #pragma unroll
        for (int e = 1; e < E_EXP; e++) mx = fmaxf(mx, lg[e]);
        float p[E_EXP];
        float sum = 0.0f;
        #pragma unroll
        for (int e = 0; e < E_EXP; e++) { p[e] = __expf(lg[e] - mx); sum += p[e]; }
        float inv = 1.0f / sum;
        #pragma unroll
        for (int e = 0; e < E_EXP; e++) { p[e] *= inv; atomicAdd(&g_psum[e], p[e]); }

        int i0 = 0;
        #pragma unroll
        for (int e = 1; e < E_EXP; e++) if (p[e] > p[i0]) i0 = e;
        int i1 = -1;
        #pragma unroll
        for (int e = 0; e < E_EXP; e++) {
            if (e == i0) continue;
            if (i1 < 0 || p[e] > p[i1]) i1 = e;
        }
        atomicAdd(&g_top1[i0], 1);

        int pos0 = atomicAdd(&g_cnt[i0], 1);
        g_list[i0 * T_TOK + pos0] = t * 2 + 0;
        g_wts[t * 2 + 0] = p[i0];
        int pos1 = atomicAdd(&g_cnt[i1], 1);
        g_list[i1 * T_TOK + pos1] = t * 2 + 1;
        g_wts[t * 2 + 1] = p[i1];
    }
}

// ---------------------------------------------------------------------------
__global__ void aux_kernel(float* out, int out_size) {
    if (threadIdx.x == 0 && blockIdx.x == 0) {
        float aux = 0.0f;
        #pragma unroll
        for (int e = 0; e < E_EXP; e++)
            aux += ((float)g_top1[e] / ((float)T_TOK + 1e-8f)) *
                   (g_psum[e] / (float)T_TOK);
        aux *= (float)E_EXP;
        if (out_size > T_TOK * D_DIM) out[T_TOK * D_DIM] = aux;
    }
}

// ---------------------------------------------------------------------------
__device__ __forceinline__ void mma16816(float* d, const uint32_t* a, const uint32_t* b) {
    asm volatile("mma.sync.aligned.m16n8k16.row.col.f32.bf16.bf16.f32 "
                 "{%0,%1,%2,%3}, {%4,%5,%6,%7}, {%8,%9}, {%0,%1,%2,%3};\n"
                 : "+f"(d[0]), "+f"(d[1]), "+f"(d[2]), "+f"(d[3])
                 : "r"(a[0]), "r"(a[1]), "r"(a[2]), "r"(a[3]), "r"(b[0]), "r"(b[1]));
}

__device__ __forceinline__ void ldsm_x4(uint32_t& r0, uint32_t& r1, uint32_t& r2,
                                        uint32_t& r3, unsigned addr) {
    asm volatile("ldmatrix.sync.aligned.m8n8.x4.shared.b16 {%0,%1,%2,%3}, [%4];\n"
                 : "=r"(r0), "=r"(r1), "=r"(r2), "=r"(r3) : "r"(addr));
}

// split two floats -> packed bf16x2 hi (first arg = low half) + packed bf16x2 lo
__device__ __forceinline__ void split2(float f0, float f1, uint32_t& hi, uint32_t& lo) {
    __nv_bfloat162 h = __floats2bfloat162_rn(f0, f1);
    float h0 = __bfloat162float(h.x), h1 = __bfloat162float(h.y);
    __nv_bfloat162 l = __floats2bfloat162_rn(f0 - h0, f1 - h1);
    hi = *(uint32_t*)&h;
    lo = *(uint32_t*)&l;
}

// ---------------------------------------------------------------------------
// TC core: register-staged fp32 global loads (issued one full slab ahead) ->
// split once per CTA into DOUBLE-BUFFERED bf16-pair u32 tiles -> ldmatrix (A)
// + scalar LDS (B) fragments -> 3 split-product MMAs. One barrier per slab.
template <int KDIM, int NDIM>
__device__ __forceinline__ void tc_core(
    const float* pa,                 // this thread's A row base (row = tid>>1)
    const float* bbase,              // W + e*K*N + n0
    uint32_t* sAh, uint32_t* sAl,    // [2][A_T]
    uint32_t* sBh, uint32_t* sBl,    // [2][B_T]
    int tid, float acc[4][4][4])
{
    // A loader: row = tid>>1, k-half = (tid&1)*8 floats
    int arow = tid >> 1, ak = (tid & 1) * 8;
    // B loader: warp w covers k-pair row w (k = 2w, 2w+1), lane covers 4 n
    int bk2 = tid >> 5, bn = (tid & 31) * 4;

    int lane = tid & 31, warp = tid >> 5;
    int wm = (warp & 1) * 64, wn = (warp >> 1) * 32;
    int g = lane >> 2, tig = lane & 3;

    // ldmatrix per-lane A address components (byte offsets within a buffer)
    unsigned uAh = (unsigned)__cvta_generic_to_shared(sAh);
    unsigned uAl = (unsigned)__cvta_generic_to_shared(sAl);
    unsigned lm_off = (((wm + (lane & 15)) * AST2) + ((lane >> 4) * 4)) * 4;

    const int NS = KDIM / 16;

    float4 ra0, ra1, rb0, rb1;

    auto load_regs = [&](int s) {
        int kk = s * 16;
        ra0 = *(const float4*)(pa + kk + ak);
        ra1 = *(const float4*)(pa + kk + ak + 4);
        const float* bs = bbase + (size_t)(kk + 2 * bk2) * NDIM + bn;
        rb0 = *(const float4*)bs;           // k even row
        rb1 = *(const float4*)(bs + NDIM);  // k odd row
    };
    auto split_store = [&](int buf) {
        uint32_t* Ah = sAh + buf * A_T;
        uint32_t* Al = sAl + buf * A_T;
        uint32_t* Bh = sBh + buf * B_T;
        uint32_t* Bl = sBl + buf * B_T;
        uint4 hv, lv;
        // A: pair along k within the row
        split2(ra0.x, ra0.y, hv.x, lv.x);
        split2(ra0.z, ra0.w, hv.y, lv.y);
        split2(ra1.x, ra1.y, hv.z, lv.z);
        split2(ra1.z, ra1.w, hv.w, lv.w);
        *(uint4*)(Ah + arow * AST2 + (ak >> 1)) = hv;
        *(uint4*)(Al + arow * AST2 + (ak >> 1)) = lv;
        // B: pair across adjacent k rows for each n
        split2(rb0.x, rb1.x, hv.x, lv.x);
        split2(rb0.y, rb1.y, hv.y, lv.y);
        split2(rb0.z, rb1.z, hv.z, lv.z);
        split2(rb0.w, rb1.w, hv.w, lv.w);
        *(uint4*)(Bh + bk2 * BST2 + bn) = hv;
        *(uint4*)(Bl + bk2 * BST2 + bn) = lv;
    };

    // prologue: slab 0 -> buf 0; LDG of slab 1 issued before first barrier
    load_regs(0);
    split_store(0);
    if (NS > 1) load_regs(1);
    __syncthreads();

    for (int s = 0; s < NS; s++) {
        int buf = s & 1;
        const uint32_t* Bh = sBh + buf * B_T;
        const uint32_t* Bl = sBl + buf * B_T;
        unsigned aHbase = uAh + (unsigned)(buf * A_T * 4) + lm_off;
        unsigned aLbase = uAl + (unsigned)(buf * A_T * 4) + lm_off;

        // B fragments for the whole slab (8+8 u32)
        uint32_t bh[4][2], bl[4][2];
        #pragma unroll
        for (int nj = 0; nj < 4; nj++) {
            int nn = wn + nj * 8 + g;
            bh[nj][0] = Bh[tig * BST2 + nn];         // k=2tig, 2tig+1
            bh[nj][1] = Bh[(tig + 4) * BST2 + nn];   // k=2tig+8, +9
            bl[nj][0] = Bl[tig * BST2 + nn];
            bl[nj][1] = Bl[(tig + 4) * BST2 + nn];
        }
        // mi-outer: A fragments via ldmatrix.x4 (r0..r3 = a0..a3)
        #pragma unroll
        for (int mi = 0; mi < 4; mi++) {
            uint32_t ah[4], al[4];
            ldsm_x4(ah[0], ah[1], ah[2], ah[3],
                    aHbase + (unsigned)(mi * 16 * AST2 * 4));
            ldsm_x4(al[0], al[1], al[2], al[3],
                    aLbase + (unsigned)(mi * 16 * AST2 * 4));
            #pragma unroll
            for (int nj = 0; nj < 4; nj++) {
                mma16816(acc[mi][nj], ah, bh[nj]);   // hi*hi
                mma16816(acc[mi][nj], ah, bl[nj]);   // hi*lo
                mma16816(acc[mi][nj], al, bh[nj]);   // lo*hi
            }
        }

        if (s + 1 < NS) {
            split_store(buf ^ 1);       // consumes regs of slab s+1; safe: the
                                        // barrier ending slab s-1 ordered all
                                        // reads of buf^1 before these writes
            if (s + 2 < NS) load_regs(s + 2);   // LDG issued a full slab early
            __syncthreads();
        }
    }
}

// ---------------------------------------------------------------------------
// GEMM1: g_h[entry][f] = relu( x[token] @ W1[e] + b1[e] )
__global__ __launch_bounds__(256, 2)
void gemm1_tc_kernel(const float* __restrict__ x,
                     const float* __restrict__ W1,
                     const float* __restrict__ b1) {
    int e = blockIdx.z;
    int n = g_cnt[e];
    int m0 = blockIdx.x * BM;
    if (m0 >= n) return;
    int n0 = blockIdx.y * BN;

    __shared__ int rows_s[BM];
    __shared__ __align__(16) uint32_t sAh[2 * A_T];
    __shared__ __align__(16) uint32_t sAl[2 * A_T];
    __shared__ __align__(16) uint32_t sBh[2 * B_T];
    __shared__ __align__(16) uint32_t sBl[2 * B_T];

    int tid = threadIdx.x;
    if (tid < BM) {
        int r = m0 + tid;
        rows_s[tid] = (r < n) ? g_list[e * T_TOK + r] : g_list[e * T_TOK];
    }
    __syncthreads();

    const float* pa = x + (size_t)(rows_s[tid >> 1] >> 1) * D_DIM;
    const float* bbase = W1 + (size_t)e * D_DIM * F_DIM + n0;

    float acc[4][4][4] = {};
    tc_core<D_DIM, F_DIM>(pa, bbase, sAh, sAl, sBh, sBl, tid, acc);

    int lane = tid & 31, warp = tid >> 5;
    int wm = (warp & 1) * 64, wn = (warp >> 1) * 32;
    int g = lane >> 2, tig = lane & 3;
    const float* b1g = b1 + (size_t)e * F_DIM;
    #pragma unroll
    for (int mi = 0; mi < 4; mi++) {
        #pragma unroll
        for (int half = 0; half < 2; half++) {
            int rl = wm + mi * 16 + g + half * 8;
            if (m0 + rl >= n) continue;
            int entry = rows_s[rl];
            float* hrow = g_h + (size_t)entry * F_DIM;
            #pragma unroll
            for (int ni = 0; ni < 4; ni++) {
                int col = n0 + wn + ni * 8 + tig * 2;
                hrow[col]     = fmaxf(acc[mi][ni][half * 2 + 0] + b1g[col], 0.0f);
                hrow[col + 1] = fmaxf(acc[mi][ni][half * 2 + 1] + b1g[col + 1], 0.0f);
            }
        }
    }
}

// ---------------------------------------------------------------------------
// GEMM2: out[t] += wt * ( g_h[entry] @ W2[e] + b2[e] )
__global__ __launch_bounds__(256, 2)
void gemm2_tc_kernel(const float* __restrict__ W2,
                     const float* __restrict__ b2,
                     float* __restrict__ out) {
    int e = blockIdx.z;
    int n = g_cnt[e];
    int m0 = blockIdx.x * BM;
    if (m0 >= n) return;
    int n0 = blockIdx.y * BN;

    __shared__ int rows_s[BM];
    __shared__ __align__(16) uint32_t sAh[2 * A_T];
    __shared__ __align__(16) uint32_t sAl[2 * A_T];
    __shared__ __align__(16) uint32_t sBh[2 * B_T];
    __shared__ __align__(16) uint32_t sBl[2 * B_T];

    int tid = threadIdx.x;
    if (tid < BM) {
        int r = m0 + tid;
        rows_s[tid] = (r < n) ? g_list[e * T_TOK + r] : g_list[e * T_TOK];
    }
    __syncthreads();

    const float* pa = g_h + (size_t)rows_s[tid >> 1] * F_DIM;
    const float* bbase = W2 + (size_t)e * F_DIM * D_DIM + n0;

    float acc[4][4][4] = {};
    tc_core<F_DIM, D_DIM>(pa, bbase, sAh, sAl, sBh, sBl, tid, acc);

    int lane = tid & 31, warp = tid >> 5;
    int wm = (warp & 1) * 64, wn = (warp >> 1) * 32;
    int g = lane >> 2, tig = lane & 3;
    const float* b2g = b2 + (size_t)e * D_DIM;
    #pragma unroll
    for (int mi = 0; mi < 4; mi++) {
        #pragma unroll
        for (int half = 0; half < 2; half++) {
            int rl = wm + mi * 16 + g + half * 8;
            if (m0 + rl >= n) continue;
            int entry = rows_s[rl];
            int t = entry >> 1;
            float wt = g_wts[entry];
            float* orow = out + (size_t)t * D_DIM;
            #pragma unroll
            for (int ni = 0; ni < 4; ni++) {
                int col = n0 + wn + ni * 8 + tig * 2;
                float v0 = (acc[mi][ni][half * 2 + 0] + b2g[col]) * wt;
                float v1 = (acc[mi][ni][half * 2 + 1] + b2g[col + 1]) * wt;
                atomicAdd(&orow[col], v0);
                atomicAdd(&orow[col + 1], v1);
            }
        }
    }
}

// ---------------------------------------------------------------------------
extern "C" void kernel_launch(void* const* d_in, const int* in_sizes, int n_in,
                              void* d_out, int out_size) {
    const float* x  = (const float*)d_in[0];
    const float* Wg = (const float*)d_in[1];
    const float* bg = (const float*)d_in[2];
    const float* W1 = (const float*)d_in[3];
    const float* b1 = (const float*)d_in[4];
    const float* W2 = (const float*)d_in[5];
    const float* b2 = (const float*)d_in[6];
    float* out = (float*)d_out;

    zero_kernel<<<256, 256>>>(out, out_size);
    gate_kernel<<<T_TOK, 256>>>(x, Wg, bg);
    aux_kernel<<<1, 32>>>(out, out_size);

    dim3 g1(T_TOK / BM, F_DIM / BN, E_EXP);      // (16, 32, 8)
    gemm1_tc_kernel<<<g1, 256>>>(x, W1, b1);

    dim3 g2(T_TOK / BM, D_DIM / BN, E_EXP);      // (16, 8, 8)
    gemm2_tc_kernel<<<g2, 256>>>(W2, b2, out);
}

// round 16
// speedup vs baseline: 2.2984x; 1.6877x over previous
#include <cuda_runtime.h>
#include <cuda_fp16.h>
#include <math.h>
#include <stdint.h>

// Problem constants
#define T_TOK 2048
#define D_DIM 1024
#define F_DIM 4096
#define E_EXP 8
#define K_TOP 2
#define NENT  (T_TOK * K_TOP)

// TC tiling
#define BM 128
#define BN 128
#define AST2 12         // fp16-pair A tile row stride (u32); LDSM-conflict-free
#define BST2 136        // fp16-pair B tile row stride (u32); frag-conflict-free
#define A_T (BM * AST2)     // 1536 u32 per buffer
#define B_T (8 * BST2)      // 1088 u32 per buffer
#define NBUF 4

// ---------------------------------------------------------------------------
// Scratch (proven set only)
__device__ float g_h[(size_t)NENT * F_DIM];
__device__ int   g_list[E_EXP * T_TOK];
__device__ float g_wts[NENT];
__device__ int   g_cnt[E_EXP];
__device__ int   g_top1[E_EXP];
__device__ float g_psum[E_EXP];

// ---------------------------------------------------------------------------
__global__ void zero_kernel(float* out, int out_size) {
    int stride = gridDim.x * blockDim.x;
    for (int i = blockIdx.x * blockDim.x + threadIdx.x; i < out_size; i += stride)
        out[i] = 0.0f;
    if (blockIdx.x == 0 && threadIdx.x < E_EXP) {
        g_cnt[threadIdx.x]  = 0;
        g_top1[threadIdx.x] = 0;
        g_psum[threadIdx.x] = 0.0f;
    }
}

// ---------------------------------------------------------------------------
__global__ void gate_kernel(const float* __restrict__ x,
                            const float* __restrict__ Wg,
                            const float* __restrict__ bg) {
    int t = blockIdx.x;
    int w = threadIdx.x >> 5;
    int lane = threadIdx.x & 31;
    const float* xr = x + (size_t)t * D_DIM;

    float s = 0.0f;
    for (int d = lane; d < D_DIM; d += 32)
        s += xr[d] * Wg[d * E_EXP + w];
    #pragma unroll
    for (int o = 16; o; o >>= 1) s += __shfl_xor_sync(0xffffffffu, s, o);

    __shared__ float lg[E_EXP];
    if (lane == 0) lg[w] = s + bg[w];
    __syncthreads();

    if (threadIdx.x == 0) {
        float mx = lg[0];
        #pragma unroll
        for (int e = 1; e < E_EXP; e++) mx = fmaxf(mx, lg[e]);
        float p[E_EXP];
        float sum = 0.0f;
        #pragma unroll
        for (int e = 0; e < E_EXP; e++) { p[e] = __expf(lg[e] - mx); sum += p[e]; }
        float inv = 1.0f / sum;
        #pragma unroll
        for (int e = 0; e < E_EXP; e++) { p[e] *= inv; atomicAdd(&g_psum[e], p[e]); }

        int i0 = 0;
        #pragma unroll
        for (int e = 1; e < E_EXP; e++) if (p[e] > p[i0]) i0 = e;
        int i1 = -1;
        #pragma unroll
        for (int e = 0; e < E_EXP; e++) {
            if (e == i0) continue;
            if (i1 < 0 || p[e] > p[i1]) i1 = e;
        }
        atomicAdd(&g_top1[i0], 1);

        int pos0 = atomicAdd(&g_cnt[i0], 1);
        g_list[i0 * T_TOK + pos0] = t * 2 + 0;
        g_wts[t * 2 + 0] = p[i0];
        int pos1 = atomicAdd(&g_cnt[i1], 1);
        g_list[i1 * T_TOK + pos1] = t * 2 + 1;
        g_wts[t * 2 + 1] = p[i1];
    }
}

// ---------------------------------------------------------------------------
__global__ void aux_kernel(float* out, int out_size) {
    if (threadIdx.x == 0 && blockIdx.x == 0) {
        float aux = 0.0f;
        #pragma unroll
        for (int e = 0; e < E_EXP; e++)
            aux += ((float)g_top1[e] / ((float)T_TOK + 1e-8f)) *
                   (g_psum[e] / (float)T_TOK);
        aux *= (float)E_EXP;
        if (out_size > T_TOK * D_DIM) out[T_TOK * D_DIM] = aux;
    }
}

// ---------------------------------------------------------------------------
__device__ __forceinline__ void mma16816(float* d, const uint32_t* a, const uint32_t* b) {
    asm volatile("mma.sync.aligned.m16n8k16.row.col.f32.f16.f16.f32 "
                 "{%0,%1,%2,%3}, {%4,%5,%6,%7}, {%8,%9}, {%0,%1,%2,%3};\n"
                 : "+f"(d[0]), "+f"(d[1]), "+f"(d[2]), "+f"(d[3])
                 : "r"(a[0]), "r"(a[1]), "r"(a[2]), "r"(a[3]), "r"(b[0]), "r"(b[1]));
}

__device__ __forceinline__ void ldsm_x4(uint32_t& r0, uint32_t& r1, uint32_t& r2,
                                        uint32_t& r3, unsigned addr) {
    asm volatile("ldmatrix.sync.aligned.m8n8.x4.shared.b16 {%0,%1,%2,%3}, [%4];\n"
                 : "=r"(r0), "=r"(r1), "=r"(r2), "=r"(r3) : "r"(addr));
}

// pack two floats -> fp16x2 (first arg = low half)
__device__ __forceinline__ uint32_t cvt2h(float f0, float f1) {
    __half2 h = __floats2half2_rn(f0, f1);
    return *(uint32_t*)&h;
}

// ---------------------------------------------------------------------------
// TC core: register-staged fp32 global loads -> fp16 pair tiles in 4 smem
// buffers -> ldmatrix (A) + scalar LDS (B) fragments -> 1 MMA per (mi,nj).
// ONE barrier per TWO k16 slabs (4-buffer rotation makes this safe: a write
// to buf[(s+2)&3] targets a buffer last read at slab s-2, previous group,
// separated by the group-end barrier).
template <int KDIM, int NDIM>
__device__ __forceinline__ void tc_core(
    const float* pa,                 // this thread's A row base (row = tid>>1)
    const float* bbase,              // W + e*K*N + n0
    uint32_t* sA, uint32_t* sB,      // [NBUF][A_T], [NBUF][B_T]
    int tid, float acc[4][4][4])
{
    // A loader: row = tid>>1, k-half = (tid&1)*8 floats
    int arow = tid >> 1, ak = (tid & 1) * 8;
    // B loader: warp w covers k-pair row w (k = 2w, 2w+1), lane covers 4 n
    int bk2 = tid >> 5, bn = (tid & 31) * 4;

    int lane = tid & 31, warp = tid >> 5;
    int wm = (warp & 1) * 64, wn = (warp >> 1) * 32;
    int g = lane >> 2, tig = lane & 3;

    unsigned uA = (unsigned)__cvta_generic_to_shared(sA);
    unsigned lm_off = (((wm + (lane & 15)) * AST2) + ((lane >> 4) * 4)) * 4;

    const int NS = KDIM / 16;     // even for both GEMMs (64, 256)

    float4 ra0, ra1, rb0, rb1;

    auto load_regs = [&](int s) {
        int kk = s * 16;
        ra0 = *(const float4*)(pa + kk + ak);
        ra1 = *(const float4*)(pa + kk + ak + 4);
        const float* bs = bbase + (size_t)(kk + 2 * bk2) * NDIM + bn;
        rb0 = *(const float4*)bs;           // k even row
        rb1 = *(const float4*)(bs + NDIM);  // k odd row
    };
    auto split_store = [&](int buf) {
        uint32_t* A = sA + buf * A_T;
        uint32_t* B = sB + buf * B_T;
        uint4 hv;
        // A: pair along k within the row
        hv.x = cvt2h(ra0.x, ra0.y);
        hv.y = cvt2h(ra0.z, ra0.w);
        hv.z = cvt2h(ra1.x, ra1.y);
        hv.w = cvt2h(ra1.z, ra1.w);
        *(uint4*)(A + arow * AST2 + (ak >> 1)) = hv;
        // B: pair across adjacent k rows for each n
        hv.x = cvt2h(rb0.x, rb1.x);
        hv.y = cvt2h(rb0.y, rb1.y);
        hv.z = cvt2h(rb0.z, rb1.z);
        hv.w = cvt2h(rb0.w, rb1.w);
        *(uint4*)(B + bk2 * BST2 + bn) = hv;
    };
    auto mma_slab = [&](int s) {
        int buf = s & (NBUF - 1);
        const uint32_t* B = sB + buf * B_T;
        unsigned aBase = uA + (unsigned)(buf * A_T * 4) + lm_off;
        uint32_t bh[4][2];
        #pragma unroll
        for (int nj = 0; nj < 4; nj++) {
            int nn = wn + nj * 8 + g;
            bh[nj][0] = B[tig * BST2 + nn];         // k=2tig, 2tig+1
            bh[nj][1] = B[(tig + 4) * BST2 + nn];   // k=2tig+8, +9
        }
        #pragma unroll
        for (int mi = 0; mi < 4; mi++) {
            uint32_t ah[4];
            ldsm_x4(ah[0], ah[1], ah[2], ah[3],
                    aBase + (unsigned)(mi * 16 * AST2 * 4));
            #pragma unroll
            for (int nj = 0; nj < 4; nj++)
                mma16816(acc[mi][nj], ah, bh[nj]);
        }
    };

    // prologue: slabs 0,1 -> bufs 0,1; regs hold slab 2
    load_regs(0); split_store(0);
    if (NS > 1) { load_regs(1); split_store(1); }
    if (NS > 2) load_regs(2);
    __syncthreads();

    for (int s = 0; s < NS; s += 2) {
        mma_slab(s);
        if (s + 2 < NS) {
            split_store((s + 2) & (NBUF - 1));     // regs of slab s+2
            if (s + 3 < NS) load_regs(s + 3);      // LDG covered by MMA below
        }
        mma_slab(s + 1);
        if (s + 3 < NS) {
            split_store((s + 3) & (NBUF - 1));
            if (s + 4 < NS) load_regs(s + 4);
        }
        if (s + 2 < NS) __syncthreads();
    }
}

// ---------------------------------------------------------------------------
// GEMM1: g_h[entry][f] = relu( x[token] @ W1[e] + b1[e] )
__global__ __launch_bounds__(256, 2)
void gemm1_tc_kernel(const float* __restrict__ x,
                     const float* __restrict__ W1,
                     const float* __restrict__ b1) {
    int e = blockIdx.z;
    int n = g_cnt[e];
    int m0 = blockIdx.x * BM;
    if (m0 >= n) return;
    int n0 = blockIdx.y * BN;

    __shared__ int rows_s[BM];
    __shared__ __align__(16) uint32_t sA[NBUF * A_T];
    __shared__ __align__(16) uint32_t sB[NBUF * B_T];

    int tid = threadIdx.x;
    if (tid < BM) {
        int r = m0 + tid;
        rows_s[tid] = (r < n) ? g_list[e * T_TOK + r] : g_list[e * T_TOK];
    }
    __syncthreads();

    const float* pa = x + (size_t)(rows_s[tid >> 1] >> 1) * D_DIM;
    const float* bbase = W1 + (size_t)e * D_DIM * F_DIM + n0;

    float acc[4][4][4] = {};
    tc_core<D_DIM, F_DIM>(pa, bbase, sA, sB, tid, acc);

    int lane = tid & 31, warp = tid >> 5;
    int wm = (warp & 1) * 64, wn = (warp >> 1) * 32;
    int g = lane >> 2, tig = lane & 3;
    const float* b1g = b1 + (size_t)e * F_DIM;
    #pragma unroll
    for (int mi = 0; mi < 4; mi++) {
        #pragma unroll
        for (int half = 0; half < 2; half++) {
            int rl = wm + mi * 16 + g + half * 8;
            if (m0 + rl >= n) continue;
            int entry = rows_s[rl];
            float* hrow = g_h + (size_t)entry * F_DIM;
            #pragma unroll
            for (int ni = 0; ni < 4; ni++) {
                int col = n0 + wn + ni * 8 + tig * 2;
                hrow[col]     = fmaxf(acc[mi][ni][half * 2 + 0] + b1g[col], 0.0f);
                hrow[col + 1] = fmaxf(acc[mi][ni][half * 2 + 1] + b1g[col + 1], 0.0f);
            }
        }
    }
}

// ---------------------------------------------------------------------------
// GEMM2: out[t] += wt * ( g_h[entry] @ W2[e] + b2[e] )
__global__ __launch_bounds__(256, 2)
void gemm2_tc_kernel(const float* __restrict__ W2,
                     const float* __restrict__ b2,
                     float* __restrict__ out) {
    int e = blockIdx.z;
    int n = g_cnt[e];
    int m0 = blockIdx.x * BM;
    if (m0 >= n) return;
    int n0 = blockIdx.y * BN;

    __shared__ int rows_s[BM];
    __shared__ __align__(16) uint32_t sA[NBUF * A_T];
    __shared__ __align__(16) uint32_t sB[NBUF * B_T];

    int tid = threadIdx.x;
    if (tid < BM) {
        int r = m0 + tid;
        rows_s[tid] = (r < n) ? g_list[e * T_TOK + r] : g_list[e * T_TOK];
    }
    __syncthreads();

    const float* pa = g_h + (size_t)rows_s[tid >> 1] * F_DIM;
    const float* bbase = W2 + (size_t)e * F_DIM * D_DIM + n0;

    float acc[4][4][4] = {};
    tc_core<F_DIM, D_DIM>(pa, bbase, sA, sB, tid, acc);

    int lane = tid & 31, warp = tid >> 5;
    int wm = (warp & 1) * 64, wn = (warp >> 1) * 32;
    int g = lane >> 2, tig = lane & 3;
    const float* b2g = b2 + (size_t)e * D_DIM;
    #pragma unroll
    for (int mi = 0; mi < 4; mi++) {
        #pragma unroll
        for (int half = 0; half < 2; half++) {
            int rl = wm + mi * 16 + g + half * 8;
            if (m0 + rl >= n) continue;
            int entry = rows_s[rl];
            int t = entry >> 1;
            float wt = g_wts[entry];
            float* orow = out + (size_t)t * D_DIM;
            #pragma unroll
            for (int ni = 0; ni < 4; ni++) {
                int col = n0 + wn + ni * 8 + tig * 2;
                float v0 = (acc[mi][ni][half * 2 + 0] + b2g[col]) * wt;
                float v1 = (acc[mi][ni][half * 2 + 1] + b2g[col + 1]) * wt;
                atomicAdd(&orow[col], v0);
                atomicAdd(&orow[col + 1], v1);
            }
        }
    }
}

// ---------------------------------------------------------------------------
extern "C" void kernel_launch(void* const* d_in, const int* in_sizes, int n_in,
                              void* d_out, int out_size) {
    const float* x  = (const float*)d_in[0];
    const float* Wg = (const float*)d_in[1];
    const float* bg = (const float*)d_in[2];
    const float* W1 = (const float*)d_in[3];
    const float* b1 = (const float*)d_in[4];
    const float* W2 = (const float*)d_in[5];
    const float* b2 = (const float*)d_in[6];
    float* out = (float*)d_out;

    zero_kernel<<<256, 256>>>(out, out_size);
    gate_kernel<<<T_TOK, 256>>>(x, Wg, bg);
    aux_kernel<<<1, 32>>>(out, out_size);

    dim3 g1(T_TOK / BM, F_DIM / BN, E_EXP);      // (16, 32, 8)
    gemm1_tc_kernel<<<g1, 256>>>(x, W1, b1);

    dim3 g2(T_TOK / BM, D_DIM / BN, E_EXP);      // (16, 8, 8)
    gemm2_tc_kernel<<<g2, 256>>>(W2, b2, out);
}